// round 3
// baseline (speedup 1.0000x reference)
#include <cuda_runtime.h>
#include <climits>

#define Bc 4
#define Fc 60082
#define Cc 14695
#define Dc 256
#define KNc 64
#define KHc 128
#define NTH 8   // his slots per block

// Scratch (no allocation allowed) — __device__ globals.
__device__ float g_u[Dc];          // W_proj @ w_ff
__device__ float g_w2v[Dc/2];      // W2 @ w_ff
__device__ float g_comp[Bc];       // company_mem . w_fc + b_fc
__device__ float g_c0;             // b_proj . w_ff
__device__ float g_c2;             // b2 . w_ff
__device__ float g_hisdot[Bc*KHc]; // leaky(rfe@W1+b1).w2v + c2 per his slot

__device__ __forceinline__ float warp_sum(float v) {
    v += __shfl_xor_sync(0xffffffffu, v, 16);
    v += __shfl_xor_sync(0xffffffffu, v, 8);
    v += __shfl_xor_sync(0xffffffffu, v, 4);
    v += __shfl_xor_sync(0xffffffffu, v, 2);
    v += __shfl_xor_sync(0xffffffffu, v, 1);
    return v; // all lanes hold full sum (butterfly)
}

// 8-float dot, both pointers 16B-aligned.
__device__ __forceinline__ float dot8(const float* __restrict__ a, const float* __restrict__ b) {
    float4 a0 = ((const float4*)a)[0], a1 = ((const float4*)a)[1];
    float4 b0 = ((const float4*)b)[0], b1 = ((const float4*)b)[1];
    return a0.x*b0.x + a0.y*b0.y + a0.z*b0.z + a0.w*b0.w
         + a1.x*b1.x + a1.y*b1.y + a1.z*b1.z + a1.w*b1.w;
}

// ---------------------------------------------------------------------------
// Kernel 1: tiny precomputations. One warp per task.
// ---------------------------------------------------------------------------
__global__ void prep_kernel(const float* __restrict__ company_emb,
                            const float* __restrict__ comp_table,
                            const float* __restrict__ W_proj,
                            const float* __restrict__ b_proj,
                            const float* __restrict__ theta,
                            const float* __restrict__ w_ff,
                            const float* __restrict__ w_fc,
                            const float* __restrict__ b_fc,
                            const float* __restrict__ W2,
                            const float* __restrict__ b2,
                            const int*   __restrict__ com_id)
{
    int wt   = (blockIdx.x * blockDim.x + threadIdx.x) >> 5;
    int lane = threadIdx.x & 31;

    if (wt < Dc) {
        float s = warp_sum(dot8(W_proj + (size_t)wt*Dc + lane*8, w_ff + lane*8));
        if (lane == 0) g_u[wt] = s;
    } else if (wt < Dc + Dc/2) {
        int j = wt - Dc;
        float s = warp_sum(dot8(W2 + (size_t)j*Dc + lane*8, w_ff + lane*8));
        if (lane == 0) g_w2v[j] = s;
    } else if (wt < Dc + Dc/2 + Bc) {
        int b   = wt - Dc - Dc/2;
        int cid = com_id[b];
        float th = theta[cid];
        float s = 0.f;
        #pragma unroll
        for (int i = 0; i < 8; i++) {
            int d = lane*8 + i;
            float m = (1.f - th) * company_emb[b*Dc + d] + th * comp_table[(size_t)cid*Dc + d];
            s += m * w_fc[d];
        }
        s = warp_sum(s);
        if (lane == 0) g_comp[b] = s + b_fc[0];
    } else if (wt == Dc + Dc/2 + Bc) {
        float s = warp_sum(dot8(b_proj + lane*8, w_ff + lane*8));
        if (lane == 0) g_c0 = s;
    } else if (wt == Dc + Dc/2 + Bc + 1) {
        float s = warp_sum(dot8(b2 + lane*8, w_ff + lane*8));
        if (lane == 0) g_c2 = s;
    }
}

// ---------------------------------------------------------------------------
// Kernel 2: his-node MLP, tiled.
// 64 blocks x 256 threads. Each block handles NTH=8 his slots; W1 is
// streamed ONCE per block (8 MB L2 total vs 64 MB before).
// Thread t: hidden unit j = t&127, node-half h = t>>7 (nodes h*4..h*4+3).
//   hisdot[slot] = leaky(rfe[f] @ W1 + b1) . w2v + c2
// ---------------------------------------------------------------------------
__global__ void __launch_bounds__(256) his_kernel(
                           const float* __restrict__ raw_field_embed,
                           const float* __restrict__ W1,
                           const float* __restrict__ b1,
                           const int*   __restrict__ his_nodes)
{
    __shared__ __align__(16) float rfe[NTH][Dc];   // 8 KB
    __shared__ float red[8][4];                    // per-warp node partials
    __shared__ float w2v_s[Dc/2];
    int t = threadIdx.x;
    int j = t & 127, h = t >> 7;
    int slot0 = blockIdx.x * NTH;

    // Load 8 rfe rows (2048 floats) via float4: 2 per thread.
    #pragma unroll
    for (int i = t; i < NTH*Dc/4; i += 256) {
        int n  = i >> 6;       // 64 float4 per row
        int c4 = i & 63;
        int f  = his_nodes[slot0 + n];
        ((float4*)rfe[n])[c4] = ((const float4*)(raw_field_embed + (size_t)f*Dc))[c4];
    }
    if (t < 128) w2v_s[t] = g_w2v[t];
    __syncthreads();

    float bj = b1[j];
    float acc0 = bj, acc1 = bj, acc2 = bj, acc3 = bj;
    int nb = h * 4;
    #pragma unroll 4
    for (int k = 0; k < Dc; k += 4) {
        // W1 column j, 4 k's (each load coalesced across j)
        float wa = W1[(size_t)(k+0)*(Dc/2) + j];
        float wb = W1[(size_t)(k+1)*(Dc/2) + j];
        float wc = W1[(size_t)(k+2)*(Dc/2) + j];
        float wd = W1[(size_t)(k+3)*(Dc/2) + j];
        float4 r0 = *(const float4*)&rfe[nb+0][k];  // smem broadcast
        float4 r1 = *(const float4*)&rfe[nb+1][k];
        float4 r2 = *(const float4*)&rfe[nb+2][k];
        float4 r3 = *(const float4*)&rfe[nb+3][k];
        acc0 += r0.x*wa + r0.y*wb + r0.z*wc + r0.w*wd;
        acc1 += r1.x*wa + r1.y*wb + r1.z*wc + r1.w*wd;
        acc2 += r2.x*wa + r2.y*wb + r2.z*wc + r2.w*wd;
        acc3 += r3.x*wa + r3.y*wb + r3.z*wc + r3.w*wd;
    }

    float wv = w2v_s[j];
    float p0 = ((acc0 >= 0.f) ? acc0 : 0.01f*acc0) * wv;
    float p1 = ((acc1 >= 0.f) ? acc1 : 0.01f*acc1) * wv;
    float p2 = ((acc2 >= 0.f) ? acc2 : 0.01f*acc2) * wv;
    float p3 = ((acc3 >= 0.f) ? acc3 : 0.01f*acc3) * wv;

    p0 = warp_sum(p0); p1 = warp_sum(p1); p2 = warp_sum(p2); p3 = warp_sum(p3);
    int warp = t >> 5, lane = t & 31;
    if (lane == 0) { red[warp][0]=p0; red[warp][1]=p1; red[warp][2]=p2; red[warp][3]=p3; }
    __syncthreads();
    if (t < NTH) {
        int n = t, hh = n >> 2, nn = n & 3;
        float s = red[hh*4+0][nn] + red[hh*4+1][nn] + red[hh*4+2][nn] + red[hh*4+3][nn];
        g_hisdot[slot0 + n] = s + g_c2;
    }
}

// ---------------------------------------------------------------------------
// Kernel 3: dense pass (streams field_table once).
//   out[b,f] = field_table[f] . u + c0 + b_ff + comp[b]
// One warp per field row; sums staged in smem so each output row gets one
// contiguous 8-float (32B-sector) store.
// ---------------------------------------------------------------------------
__global__ void __launch_bounds__(256) main_kernel(const float* __restrict__ field_table,
                                                   const float* __restrict__ b_ff,
                                                   float* __restrict__ out)
{
    __shared__ __align__(16) float u_s[Dc];
    __shared__ float add_s[Bc];
    __shared__ float sums[8];
    int t = threadIdx.x;
    u_s[t] = g_u[t];
    if (t < Bc) add_s[t] = g_comp[t] + b_ff[0] + g_c0;
    __syncthreads();

    int warp = t >> 5, lane = t & 31;
    int f = blockIdx.x * 8 + warp;
    if (f < Fc) {
        float s = dot8(field_table + (size_t)f*Dc + lane*8, u_s + lane*8);
        s = warp_sum(s);
        if (lane == 0) sums[warp] = s;
    }
    __syncthreads();
    if (t < 32) {
        int b = t >> 3, w = t & 7;
        int fo = blockIdx.x * 8 + w;
        if (fo < Fc) out[(size_t)b*Fc + fo] = sums[w] + add_s[b];
    }
}

// ---------------------------------------------------------------------------
// Kernel 4: sparse corrections. grid = (24, Bc), one node per warp.
// Overwrites touched rows with the full value (set semantics; duplicates
// write identical bits). Runs after main -> field_table rows are L2-hot.
// ---------------------------------------------------------------------------
__global__ void __launch_bounds__(256) corr_kernel(
                            const float* __restrict__ field_table,
                            const float* __restrict__ field_emb,
                            const float* __restrict__ alpha_fields,
                            const float* __restrict__ w_ff,
                            const float* __restrict__ b_ff,
                            const int*   __restrict__ now_nodes,
                            const int*   __restrict__ his_nodes,
                            float* __restrict__ out)
{
    __shared__ __align__(16) float u_s[Dc];
    __shared__ __align__(16) float wff_s[Dc];
    __shared__ int now_s[KNc], his_s[KHc];
    int b = blockIdx.y;
    int t = threadIdx.x; // 256
    u_s[t]   = g_u[t];
    wff_s[t] = w_ff[t];
    if (t < KNc) now_s[t] = now_nodes[b*KNc + t];
    if (t < KHc) his_s[t] = his_nodes[b*KHc + t];
    __syncthreads();

    float cb = g_comp[b] + b_ff[0];
    float c0 = g_c0;
    int warp = t >> 5, lane = t & 31;

    int node = blockIdx.x * 8 + warp;            // 0 .. 191
    int f = (node < KNc) ? now_s[node] : his_s[node - KNc];

    float a1 = dot8(field_table + (size_t)f*Dc + lane*8, u_s   + lane*8);
    float a2 = dot8(field_emb   + (size_t)f*Dc + lane*8, wff_s + lane*8);
    a1 = warp_sum(a1);   // base_dot (without c0)
    a2 = warp_sum(a2);   // now-term dot

    // membership: now (64 entries, 2/lane)
    bool inNow = (now_s[lane] == f) || (now_s[lane + 32] == f);
    unsigned mN = __ballot_sync(0xffffffffu, inNow);

    // membership + first matching slot in his (128 entries, 4/lane)
    int jmin = INT_MAX;
    #pragma unroll
    for (int r = 0; r < 4; r++) {
        int j = lane + r*32;
        if (his_s[j] == f && j < jmin) jmin = j;
    }
    #pragma unroll
    for (int o = 16; o > 0; o >>= 1) {
        int oth = __shfl_xor_sync(0xffffffffu, jmin, o);
        jmin = min(jmin, oth);
    }

    float alpha = alpha_fields[f];
    float val = (1.f - alpha) * (a1 + c0) + cb;
    if (mN)              val += alpha * a2;
    if (jmin != INT_MAX) val += alpha * g_hisdot[b*KHc + jmin];

    if (lane == 0) out[(size_t)b*Fc + f] = val;
}

// ---------------------------------------------------------------------------
extern "C" void kernel_launch(void* const* d_in, const int* in_sizes, int n_in,
                              void* d_out, int out_size)
{
    const float* company_emb     = (const float*)d_in[0];
    const float* field_emb       = (const float*)d_in[1];
    const float* raw_field_embed = (const float*)d_in[2];
    const float* comp_table      = (const float*)d_in[3];
    const float* field_table     = (const float*)d_in[4];
    const float* W_proj          = (const float*)d_in[5];
    const float* b_proj          = (const float*)d_in[6];
    const float* theta           = (const float*)d_in[7];
    const float* alpha_fields    = (const float*)d_in[8];
    const float* w_ff            = (const float*)d_in[9];
    const float* b_ff            = (const float*)d_in[10];
    const float* w_fc            = (const float*)d_in[11];
    const float* b_fc            = (const float*)d_in[12];
    const float* W1              = (const float*)d_in[13];
    const float* b1              = (const float*)d_in[14];
    const float* W2              = (const float*)d_in[15];
    const float* b2              = (const float*)d_in[16];
    const int*   now_nodes       = (const int*)d_in[17];
    const int*   his_nodes       = (const int*)d_in[18];
    const int*   com_id          = (const int*)d_in[19];
    float* out = (float*)d_out;

    prep_kernel<<<49, 256>>>(company_emb, comp_table, W_proj, b_proj, theta,
                             w_ff, w_fc, b_fc, W2, b2, com_id);
    his_kernel<<<(Bc*KHc)/NTH, 256>>>(raw_field_embed, W1, b1, his_nodes);
    main_kernel<<<(Fc + 7) / 8, 256>>>(field_table, b_ff, out);
    dim3 cgrid((KNc + KHc) / 8, Bc);
    corr_kernel<<<cgrid, 256>>>(field_table, field_emb, alpha_fields, w_ff, b_ff,
                                now_nodes, his_nodes, out);
}

// round 4
// speedup vs baseline: 1.1507x; 1.1507x over previous
#include <cuda_runtime.h>
#include <climits>

#define Bc 4
#define Fc 60082
#define Cc 14695
#define Dc 256
#define KNc 64
#define KHc 128
#define NTH 8    // his slots per block
#define MROWS 128 // field rows per main block (4 passes of 32)

// Scratch (no allocation allowed) — __device__ globals.
__device__ __align__(16) float g_u[Dc];   // W_proj @ w_ff
__device__ float g_w2v[Dc/2];             // W2 @ w_ff
__device__ float g_comp[Bc];              // company_mem . w_fc + b_fc
__device__ float g_c0;                    // b_proj . w_ff
__device__ float g_c2;                    // b2 . w_ff
__device__ float g_hisdot[Bc*KHc];        // leaky(rfe@W1+b1).w2v + c2 per his slot

__device__ __forceinline__ float warp_sum(float v) {
    v += __shfl_xor_sync(0xffffffffu, v, 16);
    v += __shfl_xor_sync(0xffffffffu, v, 8);
    v += __shfl_xor_sync(0xffffffffu, v, 4);
    v += __shfl_xor_sync(0xffffffffu, v, 2);
    v += __shfl_xor_sync(0xffffffffu, v, 1);
    return v;
}

__device__ __forceinline__ float dot8(const float* __restrict__ a, const float* __restrict__ b) {
    float4 a0 = ((const float4*)a)[0], a1 = ((const float4*)a)[1];
    float4 b0 = ((const float4*)b)[0], b1 = ((const float4*)b)[1];
    return a0.x*b0.x + a0.y*b0.y + a0.z*b0.z + a0.w*b0.w
         + a1.x*b1.x + a1.y*b1.y + a1.z*b1.z + a1.w*b1.w;
}

// ---------------------------------------------------------------------------
// Kernel 1: tiny precomputations. One warp per task.
// ---------------------------------------------------------------------------
__global__ void prep_kernel(const float* __restrict__ company_emb,
                            const float* __restrict__ comp_table,
                            const float* __restrict__ W_proj,
                            const float* __restrict__ b_proj,
                            const float* __restrict__ theta,
                            const float* __restrict__ w_ff,
                            const float* __restrict__ w_fc,
                            const float* __restrict__ b_fc,
                            const float* __restrict__ W2,
                            const float* __restrict__ b2,
                            const int*   __restrict__ com_id)
{
    int wt   = (blockIdx.x * blockDim.x + threadIdx.x) >> 5;
    int lane = threadIdx.x & 31;

    if (wt < Dc) {
        float s = warp_sum(dot8(W_proj + (size_t)wt*Dc + lane*8, w_ff + lane*8));
        if (lane == 0) g_u[wt] = s;
    } else if (wt < Dc + Dc/2) {
        int j = wt - Dc;
        float s = warp_sum(dot8(W2 + (size_t)j*Dc + lane*8, w_ff + lane*8));
        if (lane == 0) g_w2v[j] = s;
    } else if (wt < Dc + Dc/2 + Bc) {
        int b   = wt - Dc - Dc/2;
        int cid = com_id[b];
        float th = theta[cid];
        float s = 0.f;
        #pragma unroll
        for (int i = 0; i < 8; i++) {
            int d = lane*8 + i;
            float m = (1.f - th) * company_emb[b*Dc + d] + th * comp_table[(size_t)cid*Dc + d];
            s += m * w_fc[d];
        }
        s = warp_sum(s);
        if (lane == 0) g_comp[b] = s + b_fc[0];
    } else if (wt == Dc + Dc/2 + Bc) {
        float s = warp_sum(dot8(b_proj + lane*8, w_ff + lane*8));
        if (lane == 0) g_c0 = s;
    } else if (wt == Dc + Dc/2 + Bc + 1) {
        float s = warp_sum(dot8(b2 + lane*8, w_ff + lane*8));
        if (lane == 0) g_c2 = s;
    }
}

// ---------------------------------------------------------------------------
// Kernel 2: his-node MLP, tiled. 64 blocks x 256 threads, NTH=8 slots/block.
// W1 streamed once per block (8 MB L2 total). FFMA-bound ~2.3us.
// ---------------------------------------------------------------------------
__global__ void __launch_bounds__(256) his_kernel(
                           const float* __restrict__ raw_field_embed,
                           const float* __restrict__ W1,
                           const float* __restrict__ b1,
                           const int*   __restrict__ his_nodes)
{
    __shared__ __align__(16) float rfe[NTH][Dc];   // 8 KB
    __shared__ float red[8][4];
    __shared__ float w2v_s[Dc/2];
    int t = threadIdx.x;
    int j = t & 127, h = t >> 7;
    int slot0 = blockIdx.x * NTH;

    #pragma unroll
    for (int i = t; i < NTH*Dc/4; i += 256) {
        int n  = i >> 6;
        int c4 = i & 63;
        int f  = his_nodes[slot0 + n];
        ((float4*)rfe[n])[c4] = ((const float4*)(raw_field_embed + (size_t)f*Dc))[c4];
    }
    if (t < 128) w2v_s[t] = g_w2v[t];
    __syncthreads();

    float bj = b1[j];
    float acc0 = bj, acc1 = bj, acc2 = bj, acc3 = bj;
    int nb = h * 4;
    #pragma unroll 4
    for (int k = 0; k < Dc; k += 4) {
        float wa = W1[(size_t)(k+0)*(Dc/2) + j];
        float wb = W1[(size_t)(k+1)*(Dc/2) + j];
        float wc = W1[(size_t)(k+2)*(Dc/2) + j];
        float wd = W1[(size_t)(k+3)*(Dc/2) + j];
        float4 r0 = *(const float4*)&rfe[nb+0][k];
        float4 r1 = *(const float4*)&rfe[nb+1][k];
        float4 r2 = *(const float4*)&rfe[nb+2][k];
        float4 r3 = *(const float4*)&rfe[nb+3][k];
        acc0 += r0.x*wa + r0.y*wb + r0.z*wc + r0.w*wd;
        acc1 += r1.x*wa + r1.y*wb + r1.z*wc + r1.w*wd;
        acc2 += r2.x*wa + r2.y*wb + r2.z*wc + r2.w*wd;
        acc3 += r3.x*wa + r3.y*wb + r3.z*wc + r3.w*wd;
    }

    float wv = w2v_s[j];
    float p0 = ((acc0 >= 0.f) ? acc0 : 0.01f*acc0) * wv;
    float p1 = ((acc1 >= 0.f) ? acc1 : 0.01f*acc1) * wv;
    float p2 = ((acc2 >= 0.f) ? acc2 : 0.01f*acc2) * wv;
    float p3 = ((acc3 >= 0.f) ? acc3 : 0.01f*acc3) * wv;

    p0 = warp_sum(p0); p1 = warp_sum(p1); p2 = warp_sum(p2); p3 = warp_sum(p3);
    int warp = t >> 5, lane = t & 31;
    if (lane == 0) { red[warp][0]=p0; red[warp][1]=p1; red[warp][2]=p2; red[warp][3]=p3; }
    __syncthreads();
    if (t < NTH) {
        int n = t, hh = n >> 2, nn = n & 3;
        float s = red[hh*4+0][nn] + red[hh*4+1][nn] + red[hh*4+2][nn] + red[hh*4+3][nn];
        g_hisdot[slot0 + n] = s + g_c2;
    }
}

// ---------------------------------------------------------------------------
// Kernel 3: dense pass — restructured.
// 8 threads per row (sub = lane&7), 4 rows per warp, 4 passes of 32 rows per
// block (128 rows/block). u kept in REGISTERS; zero smem, zero barriers.
// Each thread front-batches 8 independent LDG.128 (MLP=8), reduction is
// 3 bfly shuffles per 4 rows. After bfly all 8 lanes hold the sum; lanes
// sub<4 store out[sub*Fc + f].
// ---------------------------------------------------------------------------
__global__ void __launch_bounds__(256) main_kernel(const float* __restrict__ field_table,
                                                   const float* __restrict__ b_ff,
                                                   float* __restrict__ out)
{
    int t = threadIdx.x;
    int warp = t >> 5, lane = t & 31;
    int grp = lane >> 3, sub = lane & 7;

    // u slice in registers: float4 indices sub + 8*i
    float4 uv[8];
    #pragma unroll
    for (int i = 0; i < 8; i++)
        uv[i] = ((const float4*)g_u)[sub + 8*i];

    // per-lane additive constant (only sub<4 used)
    float addv = 0.f;
    if (sub < Bc) addv = g_comp[sub] + b_ff[0] + g_c0;

    int f_base = blockIdx.x * MROWS + warp * 4 + grp;

    #pragma unroll
    for (int p = 0; p < 4; p++) {
        int f = f_base + p * 32;
        float acc = 0.f;
        if (f < Fc) {
            const float4* row = (const float4*)(field_table + (size_t)f * Dc);
            float4 v[8];
            #pragma unroll
            for (int i = 0; i < 8; i++) v[i] = row[sub + 8*i];
            #pragma unroll
            for (int i = 0; i < 8; i++)
                acc += v[i].x*uv[i].x + v[i].y*uv[i].y + v[i].z*uv[i].z + v[i].w*uv[i].w;
        }
        // reduce across the 8-lane group (masks 4,2,1 stay within group)
        acc += __shfl_xor_sync(0xffffffffu, acc, 4);
        acc += __shfl_xor_sync(0xffffffffu, acc, 2);
        acc += __shfl_xor_sync(0xffffffffu, acc, 1);
        if (f < Fc && sub < Bc)
            out[(size_t)sub * Fc + f] = acc + addv;
    }
}

// ---------------------------------------------------------------------------
// Kernel 4: sparse corrections. grid = (24, Bc), one node per warp.
// Overwrites touched rows with the full value (set semantics).
// ---------------------------------------------------------------------------
__global__ void __launch_bounds__(256) corr_kernel(
                            const float* __restrict__ field_table,
                            const float* __restrict__ field_emb,
                            const float* __restrict__ alpha_fields,
                            const float* __restrict__ w_ff,
                            const float* __restrict__ b_ff,
                            const int*   __restrict__ now_nodes,
                            const int*   __restrict__ his_nodes,
                            float* __restrict__ out)
{
    __shared__ __align__(16) float u_s[Dc];
    __shared__ __align__(16) float wff_s[Dc];
    __shared__ int now_s[KNc], his_s[KHc];
    int b = blockIdx.y;
    int t = threadIdx.x; // 256
    u_s[t]   = g_u[t];
    wff_s[t] = w_ff[t];
    if (t < KNc) now_s[t] = now_nodes[b*KNc + t];
    if (t < KHc) his_s[t] = his_nodes[b*KHc + t];
    __syncthreads();

    float cb = g_comp[b] + b_ff[0];
    float c0 = g_c0;
    int warp = t >> 5, lane = t & 31;

    int node = blockIdx.x * 8 + warp;            // 0 .. 191
    int f = (node < KNc) ? now_s[node] : his_s[node - KNc];

    float a1 = dot8(field_table + (size_t)f*Dc + lane*8, u_s   + lane*8);
    float a2 = dot8(field_emb   + (size_t)f*Dc + lane*8, wff_s + lane*8);
    a1 = warp_sum(a1);
    a2 = warp_sum(a2);

    bool inNow = (now_s[lane] == f) || (now_s[lane + 32] == f);
    unsigned mN = __ballot_sync(0xffffffffu, inNow);

    int jmin = INT_MAX;
    #pragma unroll
    for (int r = 0; r < 4; r++) {
        int j = lane + r*32;
        if (his_s[j] == f && j < jmin) jmin = j;
    }
    #pragma unroll
    for (int o = 16; o > 0; o >>= 1) {
        int oth = __shfl_xor_sync(0xffffffffu, jmin, o);
        jmin = min(jmin, oth);
    }

    float alpha = alpha_fields[f];
    float val = (1.f - alpha) * (a1 + c0) + cb;
    if (mN)              val += alpha * a2;
    if (jmin != INT_MAX) val += alpha * g_hisdot[b*KHc + jmin];

    if (lane == 0) out[(size_t)b*Fc + f] = val;
}

// ---------------------------------------------------------------------------
extern "C" void kernel_launch(void* const* d_in, const int* in_sizes, int n_in,
                              void* d_out, int out_size)
{
    const float* company_emb     = (const float*)d_in[0];
    const float* field_emb       = (const float*)d_in[1];
    const float* raw_field_embed = (const float*)d_in[2];
    const float* comp_table      = (const float*)d_in[3];
    const float* field_table     = (const float*)d_in[4];
    const float* W_proj          = (const float*)d_in[5];
    const float* b_proj          = (const float*)d_in[6];
    const float* theta           = (const float*)d_in[7];
    const float* alpha_fields    = (const float*)d_in[8];
    const float* w_ff            = (const float*)d_in[9];
    const float* b_ff            = (const float*)d_in[10];
    const float* w_fc            = (const float*)d_in[11];
    const float* b_fc            = (const float*)d_in[12];
    const float* W1              = (const float*)d_in[13];
    const float* b1              = (const float*)d_in[14];
    const float* W2              = (const float*)d_in[15];
    const float* b2              = (const float*)d_in[16];
    const int*   now_nodes       = (const int*)d_in[17];
    const int*   his_nodes       = (const int*)d_in[18];
    const int*   com_id          = (const int*)d_in[19];
    float* out = (float*)d_out;

    prep_kernel<<<49, 256>>>(company_emb, comp_table, W_proj, b_proj, theta,
                             w_ff, w_fc, b_fc, W2, b2, com_id);
    his_kernel<<<(Bc*KHc)/NTH, 256>>>(raw_field_embed, W1, b1, his_nodes);
    main_kernel<<<(Fc + MROWS - 1) / MROWS, 256>>>(field_table, b_ff, out);
    dim3 cgrid((KNc + KHc) / 8, Bc);
    corr_kernel<<<cgrid, 256>>>(field_table, field_emb, alpha_fields, w_ff, b_ff,
                                now_nodes, his_nodes, out);
}

// round 5
// speedup vs baseline: 1.3700x; 1.1905x over previous
#include <cuda_runtime.h>
#include <climits>

#define Bc 4
#define Fc 60082
#define Cc 14695
#define Dc 256
#define KNc 64
#define KHc 128
#define NTH 8                    // his slots per his block
#define MROWS 128                // field rows per main block
#define NMAIN ((Fc + MROWS - 1) / MROWS)   // 470 dense blocks
#define NHIS ((Bc*KHc)/NTH)      // 64 his blocks
#define NCORR ((KNc + KHc) / 8 * Bc)       // 96 corr blocks

// Scratch (no allocation allowed) — __device__ globals.
__device__ __align__(16) float g_u[Dc];   // W_proj @ w_ff
__device__ float g_comp[Bc];              // company_mem . w_fc + b_fc
__device__ float g_c0;                    // b_proj . w_ff
__device__ float g_hisdot[Bc*KHc];        // leaky(rfe@W1+b1).w2v + c2 per his slot
__device__ int   g_done;                  // main-blocks-finished counter

__device__ __forceinline__ float warp_sum(float v) {
    v += __shfl_xor_sync(0xffffffffu, v, 16);
    v += __shfl_xor_sync(0xffffffffu, v, 8);
    v += __shfl_xor_sync(0xffffffffu, v, 4);
    v += __shfl_xor_sync(0xffffffffu, v, 2);
    v += __shfl_xor_sync(0xffffffffu, v, 1);
    return v;
}

__device__ __forceinline__ float dot8(const float* __restrict__ a, const float* __restrict__ b) {
    float4 a0 = ((const float4*)a)[0], a1 = ((const float4*)a)[1];
    float4 b0 = ((const float4*)b)[0], b1 = ((const float4*)b)[1];
    return a0.x*b0.x + a0.y*b0.y + a0.z*b0.z + a0.w*b0.w
         + a1.x*b1.x + a1.y*b1.y + a1.z*b1.z + a1.w*b1.w;
}

// ===========================================================================
// Kernel A: his-MLP blocks (0..63) + prep blocks (64..96) in ONE grid.
// his blocks compute their own w2v (warp-per-row over W2, coalesced) and c2,
// so no cross-block dependency exists inside this kernel.
// ===========================================================================
__global__ void __launch_bounds__(256) hisprep_kernel(
                           const float* __restrict__ raw_field_embed,
                           const float* __restrict__ W1,
                           const float* __restrict__ b1,
                           const float* __restrict__ W2,
                           const float* __restrict__ b2,
                           const float* __restrict__ w_ff,
                           const float* __restrict__ company_emb,
                           const float* __restrict__ comp_table,
                           const float* __restrict__ W_proj,
                           const float* __restrict__ b_proj,
                           const float* __restrict__ theta,
                           const float* __restrict__ w_fc,
                           const float* __restrict__ b_fc,
                           const int*   __restrict__ com_id,
                           const int*   __restrict__ his_nodes)
{
    int t = threadIdx.x;
    int warp = t >> 5, lane = t & 31;

    if (blockIdx.x < NHIS) {
        // ---------------- his branch ----------------
        __shared__ __align__(16) float rfe[NTH][Dc];   // 8 KB
        __shared__ float red[8][4];
        __shared__ float w2v_s[Dc/2];
        __shared__ float c2_s;
        int j = t & 127, h = t >> 7;
        int slot0 = blockIdx.x * NTH;

        // load 8 rfe rows via float4 (2 per thread)
        #pragma unroll
        for (int i = t; i < NTH*Dc/4; i += 256) {
            int n  = i >> 6;
            int c4 = i & 63;
            int f  = his_nodes[slot0 + n];
            ((float4*)rfe[n])[c4] = ((const float4*)(raw_field_embed + (size_t)f*Dc))[c4];
        }
        // local w2v: warp w owns rows w*16 .. w*16+15 of W2 (128x256, row-major)
        #pragma unroll
        for (int r = 0; r < 16; r++) {
            int jr = warp * 16 + r;
            float s = warp_sum(dot8(W2 + (size_t)jr*Dc + lane*8, w_ff + lane*8));
            if (lane == 0) w2v_s[jr] = s;
        }
        if (warp == 0) {
            float s = warp_sum(dot8(b2 + lane*8, w_ff + lane*8));
            if (lane == 0) c2_s = s;
        }
        __syncthreads();

        float bj = b1[j];
        float acc0 = bj, acc1 = bj, acc2 = bj, acc3 = bj;
        int nb = h * 4;
        #pragma unroll 4
        for (int k = 0; k < Dc; k += 4) {
            float wa = W1[(size_t)(k+0)*(Dc/2) + j];
            float wb = W1[(size_t)(k+1)*(Dc/2) + j];
            float wc = W1[(size_t)(k+2)*(Dc/2) + j];
            float wd = W1[(size_t)(k+3)*(Dc/2) + j];
            float4 r0 = *(const float4*)&rfe[nb+0][k];
            float4 r1 = *(const float4*)&rfe[nb+1][k];
            float4 r2 = *(const float4*)&rfe[nb+2][k];
            float4 r3 = *(const float4*)&rfe[nb+3][k];
            acc0 += r0.x*wa + r0.y*wb + r0.z*wc + r0.w*wd;
            acc1 += r1.x*wa + r1.y*wb + r1.z*wc + r1.w*wd;
            acc2 += r2.x*wa + r2.y*wb + r2.z*wc + r2.w*wd;
            acc3 += r3.x*wa + r3.y*wb + r3.z*wc + r3.w*wd;
        }

        float wv = w2v_s[j];
        float p0 = ((acc0 >= 0.f) ? acc0 : 0.01f*acc0) * wv;
        float p1 = ((acc1 >= 0.f) ? acc1 : 0.01f*acc1) * wv;
        float p2 = ((acc2 >= 0.f) ? acc2 : 0.01f*acc2) * wv;
        float p3 = ((acc3 >= 0.f) ? acc3 : 0.01f*acc3) * wv;

        p0 = warp_sum(p0); p1 = warp_sum(p1); p2 = warp_sum(p2); p3 = warp_sum(p3);
        if (lane == 0) { red[warp][0]=p0; red[warp][1]=p1; red[warp][2]=p2; red[warp][3]=p3; }
        __syncthreads();
        if (t < NTH) {
            int n = t, hh = n >> 2, nn = n & 3;
            float s = red[hh*4+0][nn] + red[hh*4+1][nn] + red[hh*4+2][nn] + red[hh*4+3][nn];
            g_hisdot[slot0 + n] = s + c2_s;
        }
    } else {
        // ---------------- prep branch ----------------
        int wt = (blockIdx.x - NHIS) * 8 + warp;   // 0..263
        if (wt < Dc) {
            float s = warp_sum(dot8(W_proj + (size_t)wt*Dc + lane*8, w_ff + lane*8));
            if (lane == 0) g_u[wt] = s;
        } else if (wt < Dc + Bc) {
            int b   = wt - Dc;
            int cid = com_id[b];
            float th = theta[cid];
            float s = 0.f;
            #pragma unroll
            for (int i = 0; i < 8; i++) {
                int d = lane*8 + i;
                float m = (1.f - th) * company_emb[b*Dc + d] + th * comp_table[(size_t)cid*Dc + d];
                s += m * w_fc[d];
            }
            s = warp_sum(s);
            if (lane == 0) g_comp[b] = s + b_fc[0];
        } else if (wt == Dc + Bc) {
            float s = warp_sum(dot8(b_proj + lane*8, w_ff + lane*8));
            if (lane == 0) g_c0 = s;
        } else if (wt == Dc + Bc + 1) {
            if (lane == 0) g_done = 0;   // reset completion counter each replay
        }
    }
}

// ===========================================================================
// Kernel B: fused dense pass + sparse corrections.
//   blocks [0, NMAIN)        : dense rows (8 thr/row, 4 rows/warp, 4 passes);
//                              on exit: threadfence + atomicAdd(g_done).
//   blocks [NMAIN, NMAIN+96) : corr — compute fully in parallel with main,
//                              spin on g_done == NMAIN ONLY before the store
//                              (write-after-write ordering on touched rows).
// Deadlock-free: 96 spinners << resident capacity; deterministic output.
// ===========================================================================
__global__ void __launch_bounds__(256) fused_kernel(
                            const float* __restrict__ field_table,
                            const float* __restrict__ field_emb,
                            const float* __restrict__ alpha_fields,
                            const float* __restrict__ w_ff,
                            const float* __restrict__ b_ff,
                            const int*   __restrict__ now_nodes,
                            const int*   __restrict__ his_nodes,
                            float* __restrict__ out)
{
    int t = threadIdx.x;
    int warp = t >> 5, lane = t & 31;

    if (blockIdx.x < NMAIN) {
        // ---------------- dense branch ----------------
        int grp = lane >> 3, sub = lane & 7;

        float4 uv[8];
        #pragma unroll
        for (int i = 0; i < 8; i++)
            uv[i] = ((const float4*)g_u)[sub + 8*i];

        float addv = 0.f;
        if (sub < Bc) addv = g_comp[sub] + b_ff[0] + g_c0;

        int f_base = blockIdx.x * MROWS + warp * 4 + grp;

        #pragma unroll
        for (int p = 0; p < 4; p++) {
            int f = f_base + p * 32;
            float acc = 0.f;
            if (f < Fc) {
                const float4* row = (const float4*)(field_table + (size_t)f * Dc);
                float4 v[8];
                #pragma unroll
                for (int i = 0; i < 8; i++) v[i] = row[sub + 8*i];
                #pragma unroll
                for (int i = 0; i < 8; i++)
                    acc += v[i].x*uv[i].x + v[i].y*uv[i].y + v[i].z*uv[i].z + v[i].w*uv[i].w;
            }
            acc += __shfl_xor_sync(0xffffffffu, acc, 4);
            acc += __shfl_xor_sync(0xffffffffu, acc, 2);
            acc += __shfl_xor_sync(0xffffffffu, acc, 1);
            if (f < Fc && sub < Bc)
                out[(size_t)sub * Fc + f] = acc + addv;
        }

        // release: stores visible before counting this block done
        __threadfence();
        __syncthreads();
        if (t == 0) atomicAdd(&g_done, 1);
    } else {
        // ---------------- corr branch ----------------
        __shared__ __align__(16) float u_s[Dc];
        __shared__ __align__(16) float wff_s[Dc];
        __shared__ int now_s[KNc], his_s[KHc];
        int cid = blockIdx.x - NMAIN;      // 0..95
        int b   = cid / ((KNc + KHc)/8);   // 0..3
        int xb  = cid % ((KNc + KHc)/8);   // 0..23

        u_s[t]   = g_u[t];
        wff_s[t] = w_ff[t];
        if (t < KNc) now_s[t] = now_nodes[b*KNc + t];
        if (t < KHc) his_s[t] = his_nodes[b*KHc + t];
        __syncthreads();

        float cb = g_comp[b] + b_ff[0];
        float c0 = g_c0;

        int node = xb * 8 + warp;          // 0 .. 191
        int f = (node < KNc) ? now_s[node] : his_s[node - KNc];

        float a1 = dot8(field_table + (size_t)f*Dc + lane*8, u_s   + lane*8);
        float a2 = dot8(field_emb   + (size_t)f*Dc + lane*8, wff_s + lane*8);
        a1 = warp_sum(a1);
        a2 = warp_sum(a2);

        bool inNow = (now_s[lane] == f) || (now_s[lane + 32] == f);
        unsigned mN = __ballot_sync(0xffffffffu, inNow);

        int jmin = INT_MAX;
        #pragma unroll
        for (int r = 0; r < 4; r++) {
            int j = lane + r*32;
            if (his_s[j] == f && j < jmin) jmin = j;
        }
        #pragma unroll
        for (int o = 16; o > 0; o >>= 1) {
            int oth = __shfl_xor_sync(0xffffffffu, jmin, o);
            jmin = min(jmin, oth);
        }

        float alpha = alpha_fields[f];
        float val = (1.f - alpha) * (a1 + c0) + cb;
        if (mN)              val += alpha * a2;
        if (jmin != INT_MAX) val += alpha * g_hisdot[b*KHc + jmin];

        if (lane == 0) {
            // acquire: wait for ALL dense blocks, then overwrite (set semantics;
            // duplicate (b,f) writers store identical bits)
            volatile int* p = &g_done;
            while (*p < NMAIN) { }
            __threadfence();
            out[(size_t)b*Fc + f] = val;
        }
    }
}

// ---------------------------------------------------------------------------
extern "C" void kernel_launch(void* const* d_in, const int* in_sizes, int n_in,
                              void* d_out, int out_size)
{
    const float* company_emb     = (const float*)d_in[0];
    const float* field_emb       = (const float*)d_in[1];
    const float* raw_field_embed = (const float*)d_in[2];
    const float* comp_table      = (const float*)d_in[3];
    const float* field_table     = (const float*)d_in[4];
    const float* W_proj          = (const float*)d_in[5];
    const float* b_proj          = (const float*)d_in[6];
    const float* theta           = (const float*)d_in[7];
    const float* alpha_fields    = (const float*)d_in[8];
    const float* w_ff            = (const float*)d_in[9];
    const float* b_ff            = (const float*)d_in[10];
    const float* w_fc            = (const float*)d_in[11];
    const float* b_fc            = (const float*)d_in[12];
    const float* W1              = (const float*)d_in[13];
    const float* b1              = (const float*)d_in[14];
    const float* W2              = (const float*)d_in[15];
    const float* b2              = (const float*)d_in[16];
    const int*   now_nodes       = (const int*)d_in[17];
    const int*   his_nodes       = (const int*)d_in[18];
    const int*   com_id          = (const int*)d_in[19];
    float* out = (float*)d_out;

    // prep tasks: 256 (g_u) + 4 (g_comp) + 1 (g_c0) + 1 (counter) = 262 warps
    // -> 33 blocks of 8 warps
    hisprep_kernel<<<NHIS + 33, 256>>>(raw_field_embed, W1, b1, W2, b2, w_ff,
                                       company_emb, comp_table, W_proj, b_proj,
                                       theta, w_fc, b_fc, com_id, his_nodes);
    fused_kernel<<<NMAIN + NCORR, 256>>>(field_table, field_emb, alpha_fields,
                                         w_ff, b_ff, now_nodes, his_nodes, out);
}